// round 1
// baseline (speedup 1.0000x reference)
#include <cuda_runtime.h>
#include <math.h>
#include <stdint.h>

// Problem constants
#define B_   8
#define T_   2048
#define C_   1024
#define H_   16
#define D_   64
#define G_   8
#define GT_  256
#define L_   257          // GT_ + mean token
#define C3_  3072

// Output layout in d_out (float32):
//   out : [B,T,C]            16,777,216
//   yq  : [B,H,7,1,64]       57,344
//   yk  : [B,H,7,1,64]       57,344
//   yv  : [B,H,7,1,64]       57,344
#define OUT_OFF 0
#define YQ_OFF  16777216
#define YK_OFF  (YQ_OFF + 57344)
#define YV_OFF  (YK_OFF + 57344)

// Device scratch (static __device__ arrays: allocation-free per harness rules)
__device__ float g_qkv[(size_t)B_ * T_ * C3_];          // 192 MB
__device__ float g_mean[3 * B_ * H_ * G_ * D_];         // q/k/v group means
__device__ float g_xatt[(size_t)B_ * H_ * G_ * L_ * D_];// 67 MB
__device__ float g_xo[(size_t)B_ * T_ * C_];            // 64 MB

// ---------------------------------------------------------------------------
// Classic 128x128x8 register-tiled SGEMM, C = A[MxK] * B[KxN], row-major.
// M % 128 == 0, N % 128 == 0, K % 8 == 0 (true for all our shapes).
// ---------------------------------------------------------------------------
__global__ __launch_bounds__(256) void sgemm128(
    const float* __restrict__ A, const float* __restrict__ B,
    float* __restrict__ C, int M, int N, int K)
{
    __shared__ float As[8][128];
    __shared__ float Bs[8][128];

    const int tid = threadIdx.x;
    const int tx = tid & 15;     // 0..15  (cols of thread grid)
    const int ty = tid >> 4;     // 0..15  (rows of thread grid)
    const int row0 = blockIdx.y * 128;
    const int col0 = blockIdx.x * 128;

    float acc[8][8];
#pragma unroll
    for (int i = 0; i < 8; i++)
#pragma unroll
        for (int j = 0; j < 8; j++) acc[i][j] = 0.0f;

    const int ar = tid >> 1;          // 0..127
    const int ac = (tid & 1) * 4;     // 0 or 4
    const int br = tid >> 5;          // 0..7
    const int bc = (tid & 31) * 4;    // 0..124

    const float* Aptr = A + (size_t)(row0 + ar) * K + ac;
    const float* Bptr = B + (size_t)br * N + col0 + bc;

    for (int k0 = 0; k0 < K; k0 += 8) {
        float4 av = *(const float4*)(Aptr + k0);
        As[ac + 0][ar] = av.x;
        As[ac + 1][ar] = av.y;
        As[ac + 2][ar] = av.z;
        As[ac + 3][ar] = av.w;
        *(float4*)&Bs[br][bc] = *(const float4*)(Bptr + (size_t)k0 * N);
        __syncthreads();

#pragma unroll
        for (int k = 0; k < 8; k++) {
            float a[8], b[8];
            *(float4*)(a)     = *(const float4*)&As[k][ty * 8];
            *(float4*)(a + 4) = *(const float4*)&As[k][ty * 8 + 4];
            *(float4*)(b)     = *(const float4*)&Bs[k][tx * 8];
            *(float4*)(b + 4) = *(const float4*)&Bs[k][tx * 8 + 4];
#pragma unroll
            for (int i = 0; i < 8; i++)
#pragma unroll
                for (int j = 0; j < 8; j++)
                    acc[i][j] = fmaf(a[i], b[j], acc[i][j]);
        }
        __syncthreads();
    }

#pragma unroll
    for (int i = 0; i < 8; i++) {
        float* crow = C + (size_t)(row0 + ty * 8 + i) * N + col0 + tx * 8;
        float4 v0 = make_float4(acc[i][0], acc[i][1], acc[i][2], acc[i][3]);
        float4 v1 = make_float4(acc[i][4], acc[i][5], acc[i][6], acc[i][7]);
        *(float4*)(crow)     = v0;
        *(float4*)(crow + 4) = v1;
    }
}

// ---------------------------------------------------------------------------
// Per-(b,h,g,d) means over the 256 tokens of the group, for q, k, v.
// 3 * 65536 outputs, one thread each (coalesced over d).
// ---------------------------------------------------------------------------
__global__ void mean_kernel()
{
    int idx = blockIdx.x * blockDim.x + threadIdx.x;   // 0 .. 196607
    int d     = idx & 63;
    int g     = (idx >> 6) & 7;
    int h     = (idx >> 9) & 15;
    int b     = (idx >> 13) & 7;
    int which = idx >> 16;                              // 0=q,1=k,2=v

    const float* base = g_qkv + (size_t)(b * T_ + g * GT_) * C3_
                              + which * C_ + h * D_ + d;
    float s = 0.0f;
    for (int i = 0; i < GT_; i++) s += base[(size_t)i * C3_];
    g_mean[which * (B_ * H_ * G_ * D_) + ((b * H_ + h) * G_ + g) * D_ + d]
        = s * (1.0f / 256.0f);
}

// ---------------------------------------------------------------------------
// Causal attention, one block per (b,h,g). L=S=257, D=64.
// K/V/Q staged in padded smem (stride 65 -> conflict-free lane-per-key reads).
// Warp handles query rows r = warp, warp+8, ...; lane covers keys s = lane+32j.
// ---------------------------------------------------------------------------
#define SMEM_ATTN (3 * L_ * 65 * sizeof(float))

__global__ __launch_bounds__(256) void attn_kernel()
{
    extern __shared__ float sh[];
    float* Qs = sh;
    float* Ks = sh + L_ * 65;
    float* Vs = sh + 2 * L_ * 65;

    const int blk = blockIdx.x;
    const int g = blk & 7;
    const int h = (blk >> 3) & 15;
    const int b = blk >> 7;
    const int tid = threadIdx.x;

    // Stage Q, K, V (256 real tokens + 1 mean token)
    for (int idx = tid; idx < L_ * D_; idx += 256) {
        int s = idx >> 6, d = idx & 63;
        float q, k, v;
        if (s < GT_) {
            size_t base = (size_t)(b * T_ + g * GT_ + s) * C3_ + h * D_ + d;
            q = g_qkv[base];
            k = g_qkv[base + C_];
            v = g_qkv[base + 2 * C_];
        } else {
            int mo = ((b * H_ + h) * G_ + g) * D_ + d;
            q = g_mean[mo];
            k = g_mean[B_ * H_ * G_ * D_ + mo];
            v = g_mean[2 * B_ * H_ * G_ * D_ + mo];
        }
        Qs[s * 65 + d] = q;
        Ks[s * 65 + d] = k;
        Vs[s * 65 + d] = v;
    }
    __syncthreads();

    const int warp = tid >> 5, lane = tid & 31;

    for (int r = warp; r < L_; r += 8) {
        const int nv = r + 1;                 // causal: keys s <= r
        const float* qr = Qs + r * 65;

        float sc[9];
        float m = -1e30f;
#pragma unroll
        for (int j = 0; j < 9; j++) {
            float acc = -1e30f;
            if (j * 32 < nv) {                // warp-uniform
                int s = lane + j * 32;
                if (s < nv) {
                    const float* kr = Ks + s * 65;
                    float a = 0.0f;
#pragma unroll
                    for (int d = 0; d < 64; d++)
                        a = fmaf(qr[d], kr[d], a);
                    acc = a * 0.125f;         // 1/sqrt(64)
                }
            }
            sc[j] = acc;
            m = fmaxf(m, acc);
        }
#pragma unroll
        for (int o = 16; o; o >>= 1)
            m = fmaxf(m, __shfl_xor_sync(0xffffffffu, m, o));

        float l = 0.0f;
#pragma unroll
        for (int j = 0; j < 9; j++) {
            float e = __expf(sc[j] - m);      // masked -> exp(-1e30)=0
            sc[j] = e;
            l += e;
        }
#pragma unroll
        for (int o = 16; o; o >>= 1)
            l += __shfl_xor_sync(0xffffffffu, l, o);
        const float inv = 1.0f / l;

        float o0 = 0.0f, o1 = 0.0f;           // lane owns d=lane, d=lane+32
#pragma unroll
        for (int j = 0; j < 9; j++) {
            if (j * 32 < nv) {                // warp-uniform
                int smax = nv - j * 32;
                if (smax > 32) smax = 32;
                float pj = sc[j];
                for (int t = 0; t < smax; t++) {
                    float p = __shfl_sync(0xffffffffu, pj, t);
                    const float* vr = Vs + (j * 32 + t) * 65;
                    o0 = fmaf(p, vr[lane], o0);
                    o1 = fmaf(p, vr[lane + 32], o1);
                }
            }
        }

        float* orow = g_xatt + ((size_t)((b * H_ + h) * G_ + g) * L_ + r) * D_;
        orow[lane]      = o0 * inv;
        orow[lane + 32] = o1 * inv;
    }
}

// ---------------------------------------------------------------------------
// Tail: yq/yk (= q/k means of groups 0..6), and vl = causal_sdpa over the
// 7 group-mean tokens (values = xatt mean-token rows). One warp per (b,h).
// ---------------------------------------------------------------------------
__global__ void tail_kernel(float* __restrict__ out)
{
    const int bh = blockIdx.x;          // 0..127
    const int b = bh >> 4, h = bh & 15;
    const int lane = threadIdx.x;

    float ql0[7], ql1[7], kl0[7], kl1[7], xv0[7], xv1[7];
#pragma unroll
    for (int gi = 0; gi < 7; gi++) {
        int mo = ((b * H_ + h) * G_ + gi) * D_;
        ql0[gi] = g_mean[mo + lane];
        ql1[gi] = g_mean[mo + lane + 32];
        kl0[gi] = g_mean[B_ * H_ * G_ * D_ + mo + lane];
        kl1[gi] = g_mean[B_ * H_ * G_ * D_ + mo + lane + 32];
        size_t xa = ((size_t)((b * H_ + h) * G_ + gi) * L_ + 256) * D_;
        xv0[gi] = g_xatt[xa + lane];
        xv1[gi] = g_xatt[xa + lane + 32];

        out[YQ_OFF + (bh * 7 + gi) * 64 + lane]      = ql0[gi];
        out[YQ_OFF + (bh * 7 + gi) * 64 + lane + 32] = ql1[gi];
        out[YK_OFF + (bh * 7 + gi) * 64 + lane]      = kl0[gi];
        out[YK_OFF + (bh * 7 + gi) * 64 + lane + 32] = kl1[gi];
    }

#pragma unroll
    for (int i = 0; i < 7; i++) {
        float sc[7];
        float m = -1e30f;
#pragma unroll
        for (int j = 0; j < 7; j++) {
            float v = -1e30f;
            if (j <= i) {
                float p = ql0[i] * kl0[j] + ql1[i] * kl1[j];
#pragma unroll
                for (int o = 16; o; o >>= 1)
                    p += __shfl_xor_sync(0xffffffffu, p, o);
                v = p * 0.125f;
            }
            sc[j] = v;
            m = fmaxf(m, v);
        }
        float l = 0.0f;
#pragma unroll
        for (int j = 0; j < 7; j++) {
            float e = __expf(sc[j] - m);
            sc[j] = e;
            l += e;
        }
        float inv = 1.0f / l;
        float o0 = 0.0f, o1 = 0.0f;
#pragma unroll
        for (int j = 0; j < 7; j++) {
            o0 = fmaf(sc[j], xv0[j], o0);
            o1 = fmaf(sc[j], xv1[j], o1);
        }
        out[YV_OFF + (bh * 7 + i) * 64 + lane]      = o0 * inv;
        out[YV_OFF + (bh * 7 + i) * 64 + lane + 32] = o1 * inv;
    }
}

// ---------------------------------------------------------------------------
// xatt[b,h,g,i,d] (i<256) -> xo[b, t=g*256+i, c=h*64+d], float4 granularity.
// ---------------------------------------------------------------------------
__global__ void rearrange_kernel()
{
    int idx = blockIdx.x * blockDim.x + threadIdx.x;   // 4,194,304 float4s
    size_t e = (size_t)idx * 4;
    int d = (int)(e & 63);
    int h = (int)((e >> 6) & 15);
    int t = (int)((e >> 10) & 2047);
    int b = (int)(e >> 21);
    int g = t >> 8, i = t & 255;
    size_t src = ((size_t)((b * H_ + h) * G_ + g) * L_ + i) * D_ + d;
    *(float4*)(g_xo + e) = *(const float4*)(g_xatt + src);
}

// ---------------------------------------------------------------------------
extern "C" void kernel_launch(void* const* d_in, const int* in_sizes, int n_in,
                              void* d_out, int out_size)
{
    const float* x  = (const float*)d_in[0];
    const float* Wa = (const float*)d_in[1];
    const float* Wp = (const float*)d_in[2];
    float* out = (float*)d_out;

    void *p_qkv, *p_xo;
    cudaGetSymbolAddress(&p_qkv, g_qkv);
    cudaGetSymbolAddress(&p_xo, g_xo);

    cudaFuncSetAttribute(attn_kernel,
                         cudaFuncAttributeMaxDynamicSharedMemorySize,
                         (int)SMEM_ATTN);

    // 1) qkv = x @ W_attn     [16384 x 1024] * [1024 x 3072]
    sgemm128<<<dim3(C3_ / 128, (B_ * T_) / 128), 256>>>(
        x, Wa, (float*)p_qkv, B_ * T_, C3_, C_);

    // 2) group means of q/k/v
    mean_kernel<<<768, 256>>>();

    // 3) causal attention per (b,h,g)
    attn_kernel<<<B_ * H_ * G_, 256, SMEM_ATTN>>>();

    // 4) yq / yk / yv
    tail_kernel<<<B_ * H_, 32>>>(out);

    // 5) xatt -> xo rearrange
    rearrange_kernel<<<(B_ * T_ * C_) / 4 / 256, 256>>>();

    // 6) out = xo @ W_proj    [16384 x 1024] * [1024 x 1024]
    sgemm128<<<dim3(C_ / 128, (B_ * T_) / 128), 256>>>(
        (const float*)p_xo, Wp, out, B_ * T_, C_, C_);
}

// round 3
// speedup vs baseline: 1.6108x; 1.6108x over previous
#include <cuda_runtime.h>
#include <cuda_bf16.h>
#include <math.h>
#include <stdint.h>

// Problem constants
#define B_   8
#define T_   2048
#define C_   1024
#define H_   16
#define D_   64
#define G_   8
#define GT_  256
#define L_   257          // GT_ + mean token
#define C3_  3072

// Output layout in d_out (float32)
#define OUT_OFF 0
#define YQ_OFF  16777216
#define YK_OFF  (YQ_OFF + 57344)
#define YV_OFF  (YK_OFF + 57344)

// Device scratch
__device__ float g_qkv[(size_t)B_ * T_ * C3_];                 // 192 MB
__device__ float g_mean[3 * B_ * H_ * G_ * D_];
__device__ float g_xatt[(size_t)B_ * H_ * G_ * L_ * D_];       // 67 MB
__device__ __nv_bfloat16 g_Ahi[(size_t)B_ * T_ * C_];          // 32 MB
__device__ __nv_bfloat16 g_Alo[(size_t)B_ * T_ * C_];          // 32 MB
__device__ __nv_bfloat16 g_Bhi[(size_t)C3_ * C_];              // 6 MB
__device__ __nv_bfloat16 g_Blo[(size_t)C3_ * C_];              // 6 MB

// ===========================================================================
// HMMA GEMM:  C[M x N] = (Ahi+Alo)[M x 1024] * (Bhi+Blo)[N x 1024]^T
// 3-term bf16 split: hi*hi + hi*lo + lo*hi. K-major operands on both sides.
// CTA tile 128x128, 8 warps (2x4) of 64x32 warp tiles, K-chunk 32,
// cp.async double-buffered smem, padded row stride 40 bf16 (80 B).
// ===========================================================================
#define KDIM   1024
#define NCHUNK 32               // K / 32
#define TPAD   40               // bf16 elements per smem row (32 + 8 pad)
#define TILE_B (128 * TPAD * 2) // 10240 bytes per tile
#define STAGE_B (4 * TILE_B)    // Ahi | Alo | Bhi | Blo
#define GEMM_SMEM (2 * STAGE_B) // 81920

__device__ __forceinline__ void ldsm_x4(uint32_t& r0, uint32_t& r1,
                                        uint32_t& r2, uint32_t& r3, uint32_t a) {
    asm volatile("ldmatrix.sync.aligned.m8n8.x4.shared.b16 {%0,%1,%2,%3}, [%4];"
                 : "=r"(r0), "=r"(r1), "=r"(r2), "=r"(r3) : "r"(a));
}

__device__ __forceinline__ void mma_bf16(float* c, const uint32_t* a,
                                         const uint32_t* b) {
    asm volatile("mma.sync.aligned.m16n8k16.row.col.f32.bf16.bf16.f32 "
                 "{%0,%1,%2,%3}, {%4,%5,%6,%7}, {%8,%9}, {%0,%1,%2,%3};"
                 : "+f"(c[0]), "+f"(c[1]), "+f"(c[2]), "+f"(c[3])
                 : "r"(a[0]), "r"(a[1]), "r"(a[2]), "r"(a[3]),
                   "r"(b[0]), "r"(b[1]));
}

__device__ __forceinline__ void cp16(uint32_t saddr, const void* g) {
    asm volatile("cp.async.cg.shared.global [%0], [%1], 16;"
                 :: "r"(saddr), "l"(g));
}

__global__ __launch_bounds__(256, 1) void gemm_split(
    const __nv_bfloat16* __restrict__ Ahi, const __nv_bfloat16* __restrict__ Alo,
    const __nv_bfloat16* __restrict__ Bhi, const __nv_bfloat16* __restrict__ Blo,
    float* __restrict__ C, int N)
{
    extern __shared__ char sm[];
    const uint32_t sb = (uint32_t)__cvta_generic_to_shared(sm);
    const int tid = threadIdx.x;
    const int wid = tid >> 5, lane = tid & 31;
    const int row0 = blockIdx.y * 128;
    const int col0 = blockIdx.x * 128;

    // cp.async source/dest indexing: 512 x 16B per tile, 2 iters of 256 threads
    const int lr = tid >> 2;          // 0..63  (tile row, +64 on iter 1)
    const int lc = (tid & 3) * 16;    // byte offset within 64B row

    const char* gAhi = (const char*)Ahi + (size_t)(row0 + lr) * 2048 + lc;
    const char* gAlo = (const char*)Alo + (size_t)(row0 + lr) * 2048 + lc;
    const char* gBhi = (const char*)Bhi + (size_t)(col0 + lr) * 2048 + lc;
    const char* gBlo = (const char*)Blo + (size_t)(col0 + lr) * 2048 + lc;
    const uint32_t sRow = lr * 80 + lc;

    // warp tiling: 2 warp-rows x 4 warp-cols
    const int wm = (wid >> 2) * 64;
    const int wn = (wid & 3) * 32;

    // ldmatrix lane addressing (byte offsets within a tile)
    const uint32_t aRow = wm + (lane & 15);
    const uint32_t aCol = (lane >> 4) * 16;
    const uint32_t aOffL = aRow * 80 + aCol;
    const uint32_t bRow = wn + ((lane >> 3) & 1) * 8 + (lane & 7);
    const uint32_t bOffL = bRow * 80 + aCol;

    float acc[4][4][4];
#pragma unroll
    for (int i = 0; i < 4; i++)
#pragma unroll
        for (int j = 0; j < 4; j++)
#pragma unroll
            for (int q = 0; q < 4; q++) acc[i][j][q] = 0.0f;

    // ---- prefetch chunk 0 ----
#pragma unroll
    for (int it = 0; it < 2; it++) {
        uint32_t s = sb + sRow + it * 64 * 80;
        size_t go = (size_t)it * 64 * 2048;
        cp16(s,              gAhi + go);
        cp16(s + TILE_B,     gAlo + go);
        cp16(s + 2 * TILE_B, gBhi + go);
        cp16(s + 3 * TILE_B, gBlo + go);
    }
    asm volatile("cp.async.commit_group;");

    for (int c = 0; c < NCHUNK; c++) {
        if (c + 1 < NCHUNK) {
            const uint32_t st = sb + ((c + 1) & 1) * STAGE_B;
            const size_t gk = (size_t)(c + 1) * 64;   // 32 bf16 = 64 B
#pragma unroll
            for (int it = 0; it < 2; it++) {
                uint32_t s = st + sRow + it * 64 * 80;
                size_t go = (size_t)it * 64 * 2048 + gk;
                cp16(s,              gAhi + go);
                cp16(s + TILE_B,     gAlo + go);
                cp16(s + 2 * TILE_B, gBhi + go);
                cp16(s + 3 * TILE_B, gBlo + go);
            }
            asm volatile("cp.async.commit_group;");
            asm volatile("cp.async.wait_group 1;");
        } else {
            asm volatile("cp.async.wait_group 0;");
        }
        __syncthreads();

        const uint32_t st = sb + (c & 1) * STAGE_B;
#pragma unroll
        for (int ks = 0; ks < 2; ks++) {
            const uint32_t kb = ks * 32;
            uint32_t ah[4][4], al[4][4], bh[4][2], bl[4][2];
#pragma unroll
            for (int mt = 0; mt < 4; mt++) {
                uint32_t a0 = st + aOffL + mt * (16 * 80) + kb;
                ldsm_x4(ah[mt][0], ah[mt][1], ah[mt][2], ah[mt][3], a0);
                ldsm_x4(al[mt][0], al[mt][1], al[mt][2], al[mt][3], a0 + TILE_B);
            }
#pragma unroll
            for (int np = 0; np < 2; np++) {
                uint32_t b0 = st + 2 * TILE_B + bOffL + np * (16 * 80) + kb;
                uint32_t r0, r1, r2, r3;
                ldsm_x4(r0, r1, r2, r3, b0);
                bh[np * 2][0] = r0; bh[np * 2][1] = r2;
                bh[np * 2 + 1][0] = r1; bh[np * 2 + 1][1] = r3;
                ldsm_x4(r0, r1, r2, r3, b0 + TILE_B);
                bl[np * 2][0] = r0; bl[np * 2][1] = r2;
                bl[np * 2 + 1][0] = r1; bl[np * 2 + 1][1] = r3;
            }
#pragma unroll
            for (int mt = 0; mt < 4; mt++)
#pragma unroll
                for (int nt = 0; nt < 4; nt++) {
                    mma_bf16(acc[mt][nt], ah[mt], bh[nt]);
                    mma_bf16(acc[mt][nt], ah[mt], bl[nt]);
                    mma_bf16(acc[mt][nt], al[mt], bh[nt]);
                }
        }
        __syncthreads();
    }

    // ---- epilogue ----
    const int erow = row0 + wm + (lane >> 2);
    const int ecol = col0 + wn + (lane & 3) * 2;
#pragma unroll
    for (int mt = 0; mt < 4; mt++) {
#pragma unroll
        for (int nt = 0; nt < 4; nt++) {
            float* p0 = C + (size_t)(erow + mt * 16) * N + ecol + nt * 8;
            float* p1 = p0 + 8 * N;
            *(float2*)p0 = make_float2(acc[mt][nt][0], acc[mt][nt][1]);
            *(float2*)p1 = make_float2(acc[mt][nt][2], acc[mt][nt][3]);
        }
    }
}

// ===========================================================================
// bf16 split helpers
// ===========================================================================
__device__ __forceinline__ void split_bf16(float a, unsigned short& h, unsigned short& l) {
    __nv_bfloat16 hb = __float2bfloat16(a);
    __nv_bfloat16 lb = __float2bfloat16(a - __bfloat162float(hb));
    h = __bfloat16_as_ushort(hb);
    l = __bfloat16_as_ushort(lb);
}

// x [16384,1024] f32 -> Ahi/Alo [16384,1024] bf16
__global__ void conv_split_A(const float* __restrict__ src,
                             __nv_bfloat16* __restrict__ hi,
                             __nv_bfloat16* __restrict__ lo)
{
    int idx = blockIdx.x * blockDim.x + threadIdx.x;   // 4,194,304
    size_t e = (size_t)idx * 4;
    float4 v = *(const float4*)(src + e);
    unsigned short h0, l0, h1, l1, h2, l2, h3, l3;
    split_bf16(v.x, h0, l0); split_bf16(v.y, h1, l1);
    split_bf16(v.z, h2, l2); split_bf16(v.w, h3, l3);
    uint2 Hh, Ll;
    Hh.x = (uint32_t)h0 | ((uint32_t)h1 << 16);
    Hh.y = (uint32_t)h2 | ((uint32_t)h3 << 16);
    Ll.x = (uint32_t)l0 | ((uint32_t)l1 << 16);
    Ll.y = (uint32_t)l2 | ((uint32_t)l3 << 16);
    *(uint2*)(hi + e) = Hh;
    *(uint2*)(lo + e) = Ll;
}

// Fused rearrange + split: xatt[b,h,g,i<256,d] -> A[t=b*2048+g*256+i, c=h*64+d]
__global__ void conv_split_xatt(__nv_bfloat16* __restrict__ hi,
                                __nv_bfloat16* __restrict__ lo)
{
    int idx = blockIdx.x * blockDim.x + threadIdx.x;   // 4,194,304
    size_t e = (size_t)idx * 4;
    int d = (int)(e & 63);
    int h = (int)((e >> 6) & 15);
    int t = (int)((e >> 10) & 2047);
    int b = (int)(e >> 21);
    int g = t >> 8, i = t & 255;
    size_t src = ((size_t)((b * H_ + h) * G_ + g) * L_ + i) * D_ + d;
    float4 v = *(const float4*)(g_xatt + src);
    unsigned short h0, l0, h1, l1, h2, l2, h3, l3;
    split_bf16(v.x, h0, l0); split_bf16(v.y, h1, l1);
    split_bf16(v.z, h2, l2); split_bf16(v.w, h3, l3);
    uint2 Hh, Ll;
    Hh.x = (uint32_t)h0 | ((uint32_t)h1 << 16);
    Hh.y = (uint32_t)h2 | ((uint32_t)h3 << 16);
    Ll.x = (uint32_t)l0 | ((uint32_t)l1 << 16);
    Ll.y = (uint32_t)l2 | ((uint32_t)l3 << 16);
    size_t base = (size_t)(b * T_ + t) * C_ + h * D_ + d;
    *(uint2*)(hi + base) = Hh;
    *(uint2*)(lo + base) = Ll;
}

// W [1024,Nw] f32 -> Bt hi/lo [Nw,1024] bf16 (transposed, K-major)
__global__ __launch_bounds__(256) void conv_split_W(
    const float* __restrict__ W,
    __nv_bfloat16* __restrict__ hi, __nv_bfloat16* __restrict__ lo, int Nw)
{
    __shared__ float tile[32][33];
    const int tx = threadIdx.x & 31, ty = threadIdx.x >> 5;
    const int k0 = blockIdx.y * 32, n0 = blockIdx.x * 32;
#pragma unroll
    for (int it = 0; it < 4; it++) {
        int r = ty + it * 8;
        tile[r][tx] = W[(size_t)(k0 + r) * Nw + n0 + tx];
    }
    __syncthreads();
#pragma unroll
    for (int it = 0; it < 4; it++) {
        int n = ty + it * 8;
        float a = tile[tx][n];
        unsigned short hu, lu;
        split_bf16(a, hu, lu);
        size_t base = (size_t)(n0 + n) * KDIM + k0 + tx;
        hi[base] = __ushort_as_bfloat16(hu);
        lo[base] = __ushort_as_bfloat16(lu);
    }
}

// ===========================================================================
// Per-(b,h,g,d) means over the 256 tokens of the group, for q, k, v.
// ===========================================================================
__global__ void mean_kernel()
{
    int idx = blockIdx.x * blockDim.x + threadIdx.x;   // 0 .. 196607
    int d     = idx & 63;
    int g     = (idx >> 6) & 7;
    int h     = (idx >> 9) & 15;
    int b     = (idx >> 13) & 7;
    int which = idx >> 16;

    const float* base = g_qkv + (size_t)(b * T_ + g * GT_) * C3_
                              + which * C_ + h * D_ + d;
    float s = 0.0f;
    for (int i = 0; i < GT_; i++) s += base[(size_t)i * C3_];
    g_mean[which * (B_ * H_ * G_ * D_) + ((b * H_ + h) * G_ + g) * D_ + d]
        = s * (1.0f / 256.0f);
}

// ===========================================================================
// Causal attention, one block per (b,h,g). L=S=257, D=64.
// ===========================================================================
#define SMEM_ATTN (3 * L_ * 65 * sizeof(float))

__global__ __launch_bounds__(256) void attn_kernel()
{
    extern __shared__ float sh[];
    float* Qs = sh;
    float* Ks = sh + L_ * 65;
    float* Vs = sh + 2 * L_ * 65;

    const int blk = blockIdx.x;
    const int g = blk & 7;
    const int h = (blk >> 3) & 15;
    const int b = blk >> 7;
    const int tid = threadIdx.x;

    for (int idx = tid; idx < L_ * D_; idx += 256) {
        int s = idx >> 6, d = idx & 63;
        float q, k, v;
        if (s < GT_) {
            size_t base = (size_t)(b * T_ + g * GT_ + s) * C3_ + h * D_ + d;
            q = g_qkv[base];
            k = g_qkv[base + C_];
            v = g_qkv[base + 2 * C_];
        } else {
            int mo = ((b * H_ + h) * G_ + g) * D_ + d;
            q = g_mean[mo];
            k = g_mean[B_ * H_ * G_ * D_ + mo];
            v = g_mean[2 * B_ * H_ * G_ * D_ + mo];
        }
        Qs[s * 65 + d] = q;
        Ks[s * 65 + d] = k;
        Vs[s * 65 + d] = v;
    }
    __syncthreads();

    const int warp = tid >> 5, lane = tid & 31;

    for (int r = warp; r < L_; r += 8) {
        const int nv = r + 1;
        const float* qr = Qs + r * 65;

        float sc[9];
        float m = -1e30f;
#pragma unroll
        for (int j = 0; j < 9; j++) {
            float acc = -1e30f;
            if (j * 32 < nv) {
                int s = lane + j * 32;
                if (s < nv) {
                    const float* kr = Ks + s * 65;
                    float a = 0.0f;
#pragma unroll
                    for (int d = 0; d < 64; d++)
                        a = fmaf(qr[d], kr[d], a);
                    acc = a * 0.125f;
                }
            }
            sc[j] = acc;
            m = fmaxf(m, acc);
        }
#pragma unroll
        for (int o = 16; o; o >>= 1)
            m = fmaxf(m, __shfl_xor_sync(0xffffffffu, m, o));

        float l = 0.0f;
#pragma unroll
        for (int j = 0; j < 9; j++) {
            float e = __expf(sc[j] - m);
            sc[j] = e;
            l += e;
        }
#pragma unroll
        for (int o = 16; o; o >>= 1)
            l += __shfl_xor_sync(0xffffffffu, l, o);
        const float inv = 1.0f / l;

        float o0 = 0.0f, o1 = 0.0f;
#pragma unroll
        for (int j = 0; j < 9; j++) {
            if (j * 32 < nv) {
                int smax = nv - j * 32;
                if (smax > 32) smax = 32;
                float pj = sc[j];
                for (int t = 0; t < smax; t++) {
                    float p = __shfl_sync(0xffffffffu, pj, t);
                    const float* vr = Vs + (j * 32 + t) * 65;
                    o0 = fmaf(p, vr[lane], o0);
                    o1 = fmaf(p, vr[lane + 32], o1);
                }
            }
        }

        float* orow = g_xatt + ((size_t)((b * H_ + h) * G_ + g) * L_ + r) * D_;
        orow[lane]      = o0 * inv;
        orow[lane + 32] = o1 * inv;
    }
}

// ===========================================================================
// Tail: yq/yk and 7x7 group-level causal attention (yv). One warp per (b,h).
// ===========================================================================
__global__ void tail_kernel(float* __restrict__ out)
{
    const int bh = blockIdx.x;
    const int b = bh >> 4, h = bh & 15;
    const int lane = threadIdx.x;

    float ql0[7], ql1[7], kl0[7], kl1[7], xv0[7], xv1[7];
#pragma unroll
    for (int gi = 0; gi < 7; gi++) {
        int mo = ((b * H_ + h) * G_ + gi) * D_;
        ql0[gi] = g_mean[mo + lane];
        ql1[gi] = g_mean[mo + lane + 32];
        kl0[gi] = g_mean[B_ * H_ * G_ * D_ + mo + lane];
        kl1[gi] = g_mean[B_ * H_ * G_ * D_ + mo + lane + 32];
        size_t xa = ((size_t)((b * H_ + h) * G_ + gi) * L_ + 256) * D_;
        xv0[gi] = g_xatt[xa + lane];
        xv1[gi] = g_xatt[xa + lane + 32];

        out[YQ_OFF + (bh * 7 + gi) * 64 + lane]      = ql0[gi];
        out[YQ_OFF + (bh * 7 + gi) * 64 + lane + 32] = ql1[gi];
        out[YK_OFF + (bh * 7 + gi) * 64 + lane]      = kl0[gi];
        out[YK_OFF + (bh * 7 + gi) * 64 + lane + 32] = kl1[gi];
    }

#pragma unroll
    for (int i = 0; i < 7; i++) {
        float sc[7];
        float m = -1e30f;
#pragma unroll
        for (int j = 0; j < 7; j++) {
            float v = -1e30f;
            if (j <= i) {
                float p = ql0[i] * kl0[j] + ql1[i] * kl1[j];
#pragma unroll
                for (int o = 16; o; o >>= 1)
                    p += __shfl_xor_sync(0xffffffffu, p, o);
                v = p * 0.125f;
            }
            sc[j] = v;
            m = fmaxf(m, v);
        }
        float l = 0.0f;
#pragma unroll
        for (int j = 0; j < 7; j++) {
            float e = __expf(sc[j] - m);
            sc[j] = e;
            l += e;
        }
        float inv = 1.0f / l;
        float o0 = 0.0f, o1 = 0.0f;
#pragma unroll
        for (int j = 0; j < 7; j++) {
            o0 = fmaf(sc[j], xv0[j], o0);
            o1 = fmaf(sc[j], xv1[j], o1);
        }
        out[YV_OFF + (bh * 7 + i) * 64 + lane]      = o0 * inv;
        out[YV_OFF + (bh * 7 + i) * 64 + lane + 32] = o1 * inv;
    }
}

// ===========================================================================
extern "C" void kernel_launch(void* const* d_in, const int* in_sizes, int n_in,
                              void* d_out, int out_size)
{
    const float* x  = (const float*)d_in[0];
    const float* Wa = (const float*)d_in[1];
    const float* Wp = (const float*)d_in[2];
    float* out = (float*)d_out;

    void *p_qkv, *p_Ahi, *p_Alo, *p_Bhi, *p_Blo;
    cudaGetSymbolAddress(&p_qkv, g_qkv);
    cudaGetSymbolAddress(&p_Ahi, g_Ahi);
    cudaGetSymbolAddress(&p_Alo, g_Alo);
    cudaGetSymbolAddress(&p_Bhi, g_Bhi);
    cudaGetSymbolAddress(&p_Blo, g_Blo);

    cudaFuncSetAttribute(attn_kernel,
                         cudaFuncAttributeMaxDynamicSharedMemorySize, (int)SMEM_ATTN);
    cudaFuncSetAttribute(gemm_split,
                         cudaFuncAttributeMaxDynamicSharedMemorySize, GEMM_SMEM);

    // 1) split x and W_attn to bf16 hi/lo
    conv_split_A<<<16384, 256>>>(x, (__nv_bfloat16*)p_Ahi, (__nv_bfloat16*)p_Alo);
    conv_split_W<<<dim3(C3_ / 32, C_ / 32), 256>>>(
        Wa, (__nv_bfloat16*)p_Bhi, (__nv_bfloat16*)p_Blo, C3_);

    // 2) qkv = x @ W_attn  (HMMA, 3-term bf16 split)
    gemm_split<<<dim3(C3_ / 128, (B_ * T_) / 128), 256, GEMM_SMEM>>>(
        (const __nv_bfloat16*)p_Ahi, (const __nv_bfloat16*)p_Alo,
        (const __nv_bfloat16*)p_Bhi, (const __nv_bfloat16*)p_Blo,
        (float*)p_qkv, C3_);

    // 3) group means of q/k/v
    mean_kernel<<<768, 256>>>();

    // 4) causal attention per (b,h,g)
    attn_kernel<<<B_ * H_ * G_, 256, SMEM_ATTN>>>();

    // 5) yq / yk / yv
    tail_kernel<<<B_ * H_, 32>>>(out);

    // 6) fused rearrange + split of xatt; split W_proj
    conv_split_xatt<<<16384, 256>>>((__nv_bfloat16*)p_Ahi, (__nv_bfloat16*)p_Alo);
    conv_split_W<<<dim3(C_ / 32, C_ / 32), 256>>>(
        Wp, (__nv_bfloat16*)p_Bhi, (__nv_bfloat16*)p_Blo, C_);

    // 7) out = xo @ W_proj
    gemm_split<<<dim3(C_ / 128, (B_ * T_) / 128), 256, GEMM_SMEM>>>(
        (const __nv_bfloat16*)p_Ahi, (const __nv_bfloat16*)p_Alo,
        (const __nv_bfloat16*)p_Bhi, (const __nv_bfloat16*)p_Blo,
        out, C_);
}

// round 4
// speedup vs baseline: 2.3526x; 1.4605x over previous
#include <cuda_runtime.h>
#include <cuda_fp16.h>
#include <math.h>
#include <stdint.h>

// Problem constants
#define B_   8
#define T_   2048
#define C_   1024
#define H_   16
#define D_   64
#define G_   8
#define GT_  256
#define L_   257          // GT_ + mean token
#define C3_  3072

// Output layout in d_out (float32)
#define OUT_OFF 0
#define YQ_OFF  16777216
#define YK_OFF  (YQ_OFF + 57344)
#define YV_OFF  (YK_OFF + 57344)

// Device scratch
__device__ float g_qkv[(size_t)B_ * T_ * C3_];                 // 192 MB
__device__ float g_mean[3 * B_ * H_ * G_ * D_];
__device__ float g_xatt[(size_t)B_ * H_ * G_ * L_ * D_];       // 67 MB
__device__ __half g_Af16[(size_t)B_ * T_ * C_];                // 32 MB
__device__ __half g_Bf16[(size_t)C3_ * C_];                    // 6 MB

// ===========================================================================
// HMMA fp16 GEMM:  C[M x N] = A[M x 1024] * Bt[N x 1024]^T
// CTA tile 128x128, 8 warps (2x4) of 64x32 warp tiles, K-chunk 32,
// 3-stage cp.async pipeline, padded smem row stride 40 halves (80 B).
// ===========================================================================
#define KDIM    1024
#define NCHUNK  32              // K / 32
#define TPAD    40              // halves per smem row (32 + 8 pad)
#define TILE_B  (128 * TPAD * 2)  // 10240 bytes per operand tile
#define STAGE_B (2 * TILE_B)      // A | B
#define NSTAGE  3
#define GEMM_SMEM (NSTAGE * STAGE_B)   // 61440

__device__ __forceinline__ void ldsm_x4(uint32_t& r0, uint32_t& r1,
                                        uint32_t& r2, uint32_t& r3, uint32_t a) {
    asm volatile("ldmatrix.sync.aligned.m8n8.x4.shared.b16 {%0,%1,%2,%3}, [%4];"
                 : "=r"(r0), "=r"(r1), "=r"(r2), "=r"(r3) : "r"(a));
}

__device__ __forceinline__ void mma_f16(float* c, const uint32_t* a,
                                        const uint32_t* b) {
    asm volatile("mma.sync.aligned.m16n8k16.row.col.f32.f16.f16.f32 "
                 "{%0,%1,%2,%3}, {%4,%5,%6,%7}, {%8,%9}, {%0,%1,%2,%3};"
                 : "+f"(c[0]), "+f"(c[1]), "+f"(c[2]), "+f"(c[3])
                 : "r"(a[0]), "r"(a[1]), "r"(a[2]), "r"(a[3]),
                   "r"(b[0]), "r"(b[1]));
}

__device__ __forceinline__ void cp16(uint32_t saddr, const void* g) {
    asm volatile("cp.async.cg.shared.global [%0], [%1], 16;"
                 :: "r"(saddr), "l"(g));
}

__global__ __launch_bounds__(256) void gemm_f16(
    const __half* __restrict__ A, const __half* __restrict__ Bt,
    float* __restrict__ C, int N)
{
    extern __shared__ char sm[];
    const uint32_t sb = (uint32_t)__cvta_generic_to_shared(sm);
    const int tid = threadIdx.x;
    const int wid = tid >> 5, lane = tid & 31;
    const int row0 = blockIdx.y * 128;
    const int col0 = blockIdx.x * 128;

    // cp.async indexing: per tile 128 rows x 64 B; 2 iters x 256 thr x 16 B
    const int lr = tid >> 2;          // 0..63
    const int lc = (tid & 3) * 16;    // byte offset in 64B row

    const char* gA = (const char*)A + (size_t)(row0 + lr) * 2048 + lc;
    const char* gB = (const char*)Bt + (size_t)(col0 + lr) * 2048 + lc;
    const uint32_t sRow = lr * 80 + lc;

    // warp tiling: 2 warp-rows x 4 warp-cols (64x32 per warp)
    const int wm = (wid >> 2) * 64;
    const int wn = (wid & 3) * 32;

    const uint32_t aOffL = (wm + (lane & 15)) * 80 + (lane >> 4) * 16;
    const uint32_t bOffL = (wn + ((lane >> 3) & 1) * 8 + (lane & 7)) * 80
                         + (lane >> 4) * 16;

    float acc[4][4][4];
#pragma unroll
    for (int i = 0; i < 4; i++)
#pragma unroll
        for (int j = 0; j < 4; j++)
#pragma unroll
            for (int q = 0; q < 4; q++) acc[i][j][q] = 0.0f;

    // prologue: prefetch chunks 0 and 1
#pragma unroll
    for (int pc = 0; pc < 2; pc++) {
        const uint32_t st = sb + pc * STAGE_B;
        const size_t gk = (size_t)pc * 64;
#pragma unroll
        for (int it = 0; it < 2; it++) {
            uint32_t s = st + sRow + it * 64 * 80;
            size_t go = (size_t)it * 64 * 2048 + gk;
            cp16(s,          gA + go);
            cp16(s + TILE_B, gB + go);
        }
        asm volatile("cp.async.commit_group;");
    }

    for (int c = 0; c < NCHUNK; c++) {
        __syncthreads();   // all warps done with the buffer being overwritten
        if (c + 2 < NCHUNK) {
            const uint32_t st = sb + ((c + 2) % 3) * STAGE_B;
            const size_t gk = (size_t)(c + 2) * 64;
#pragma unroll
            for (int it = 0; it < 2; it++) {
                uint32_t s = st + sRow + it * 64 * 80;
                size_t go = (size_t)it * 64 * 2048 + gk;
                cp16(s,          gA + go);
                cp16(s + TILE_B, gB + go);
            }
            asm volatile("cp.async.commit_group;");
            asm volatile("cp.async.wait_group 2;");
        } else if (c + 1 < NCHUNK) {
            asm volatile("cp.async.wait_group 1;");
        } else {
            asm volatile("cp.async.wait_group 0;");
        }
        __syncthreads();

        const uint32_t st = sb + (c % 3) * STAGE_B;
#pragma unroll
        for (int ks = 0; ks < 2; ks++) {
            const uint32_t kb = ks * 32;
            uint32_t a[4][4], b[4][2];
#pragma unroll
            for (int mt = 0; mt < 4; mt++)
                ldsm_x4(a[mt][0], a[mt][1], a[mt][2], a[mt][3],
                        st + aOffL + mt * (16 * 80) + kb);
#pragma unroll
            for (int np = 0; np < 2; np++) {
                uint32_t r0, r1, r2, r3;
                ldsm_x4(r0, r1, r2, r3,
                        st + TILE_B + bOffL + np * (16 * 80) + kb);
                b[np * 2][0] = r0;     b[np * 2][1] = r2;
                b[np * 2 + 1][0] = r1; b[np * 2 + 1][1] = r3;
            }
#pragma unroll
            for (int mt = 0; mt < 4; mt++)
#pragma unroll
                for (int nt = 0; nt < 4; nt++)
                    mma_f16(acc[mt][nt], a[mt], b[nt]);
        }
    }

    // epilogue
    const int erow = row0 + wm + (lane >> 2);
    const int ecol = col0 + wn + (lane & 3) * 2;
#pragma unroll
    for (int mt = 0; mt < 4; mt++) {
#pragma unroll
        for (int nt = 0; nt < 4; nt++) {
            float* p0 = C + (size_t)(erow + mt * 16) * N + ecol + nt * 8;
            float* p1 = p0 + 8 * N;
            *(float2*)p0 = make_float2(acc[mt][nt][0], acc[mt][nt][1]);
            *(float2*)p1 = make_float2(acc[mt][nt][2], acc[mt][nt][3]);
        }
    }
}

// ===========================================================================
// Conversions
// ===========================================================================
// x [16384,1024] f32 -> A [16384,1024] fp16
__global__ void conv_A(const float* __restrict__ src, __half* __restrict__ dst)
{
    int idx = blockIdx.x * blockDim.x + threadIdx.x;   // 4,194,304
    size_t e = (size_t)idx * 4;
    float4 v = *(const float4*)(src + e);
    __half2 h01 = __floats2half2_rn(v.x, v.y);
    __half2 h23 = __floats2half2_rn(v.z, v.w);
    uint2 o;
    o.x = *(uint32_t*)&h01;
    o.y = *(uint32_t*)&h23;
    *(uint2*)(dst + e) = o;
}

// Fused rearrange + convert: xatt[b,h,g,i<256,d] -> A[t, c=h*64+d] fp16
__global__ void conv_xatt(__half* __restrict__ dst)
{
    int idx = blockIdx.x * blockDim.x + threadIdx.x;   // 4,194,304
    size_t e = (size_t)idx * 4;
    int d = (int)(e & 63);
    int h = (int)((e >> 6) & 15);
    int t = (int)((e >> 10) & 2047);
    int b = (int)(e >> 21);
    int g = t >> 8, i = t & 255;
    size_t src = ((size_t)((b * H_ + h) * G_ + g) * L_ + i) * D_ + d;
    float4 v = *(const float4*)(g_xatt + src);
    __half2 h01 = __floats2half2_rn(v.x, v.y);
    __half2 h23 = __floats2half2_rn(v.z, v.w);
    uint2 o;
    o.x = *(uint32_t*)&h01;
    o.y = *(uint32_t*)&h23;
    size_t base = (size_t)(b * T_ + t) * C_ + h * D_ + d;
    *(uint2*)(dst + base) = o;
}

// W [1024,Nw] f32 -> Bt [Nw,1024] fp16 (transposed, K-major)
__global__ __launch_bounds__(256) void conv_W(
    const float* __restrict__ W, __half* __restrict__ dst, int Nw)
{
    __shared__ float tile[32][33];
    const int tx = threadIdx.x & 31, ty = threadIdx.x >> 5;
    const int k0 = blockIdx.y * 32, n0 = blockIdx.x * 32;
#pragma unroll
    for (int it = 0; it < 4; it++) {
        int r = ty + it * 8;
        tile[r][tx] = W[(size_t)(k0 + r) * Nw + n0 + tx];
    }
    __syncthreads();
#pragma unroll
    for (int it = 0; it < 4; it++) {
        int n = ty + it * 8;
        dst[(size_t)(n0 + n) * KDIM + k0 + tx] = __float2half_rn(tile[tx][n]);
    }
}

// ===========================================================================
// Per-(b,h,g,d) means over the 256 tokens of the group, for q, k, v.
// ===========================================================================
__global__ void mean_kernel()
{
    int idx = blockIdx.x * blockDim.x + threadIdx.x;   // 0 .. 196607
    int d     = idx & 63;
    int g     = (idx >> 6) & 7;
    int h     = (idx >> 9) & 15;
    int b     = (idx >> 13) & 7;
    int which = idx >> 16;

    const float* base = g_qkv + (size_t)(b * T_ + g * GT_) * C3_
                              + which * C_ + h * D_ + d;
    float s = 0.0f;
    for (int i = 0; i < GT_; i++) s += base[(size_t)i * C3_];
    g_mean[which * (B_ * H_ * G_ * D_) + ((b * H_ + h) * G_ + g) * D_ + d]
        = s * (1.0f / 256.0f);
}

// ===========================================================================
// Causal attention, one block per (b,h,g). L=S=257, D=64.
// ===========================================================================
#define SMEM_ATTN (3 * L_ * 65 * sizeof(float))

__global__ __launch_bounds__(256) void attn_kernel()
{
    extern __shared__ float sh[];
    float* Qs = sh;
    float* Ks = sh + L_ * 65;
    float* Vs = sh + 2 * L_ * 65;

    const int blk = blockIdx.x;
    const int g = blk & 7;
    const int h = (blk >> 3) & 15;
    const int b = blk >> 7;
    const int tid = threadIdx.x;

    for (int idx = tid; idx < L_ * D_; idx += 256) {
        int s = idx >> 6, d = idx & 63;
        float q, k, v;
        if (s < GT_) {
            size_t base = (size_t)(b * T_ + g * GT_ + s) * C3_ + h * D_ + d;
            q = g_qkv[base];
            k = g_qkv[base + C_];
            v = g_qkv[base + 2 * C_];
        } else {
            int mo = ((b * H_ + h) * G_ + g) * D_ + d;
            q = g_mean[mo];
            k = g_mean[B_ * H_ * G_ * D_ + mo];
            v = g_mean[2 * B_ * H_ * G_ * D_ + mo];
        }
        Qs[s * 65 + d] = q;
        Ks[s * 65 + d] = k;
        Vs[s * 65 + d] = v;
    }
    __syncthreads();

    const int warp = tid >> 5, lane = tid & 31;

    for (int r = warp; r < L_; r += 8) {
        const int nv = r + 1;
        const float* qr = Qs + r * 65;

        float sc[9];
        float m = -1e30f;
#pragma unroll
        for (int j = 0; j < 9; j++) {
            float acc = -1e30f;
            if (j * 32 < nv) {
                int s = lane + j * 32;
                if (s < nv) {
                    const float* kr = Ks + s * 65;
                    float a = 0.0f;
#pragma unroll
                    for (int d = 0; d < 64; d++)
                        a = fmaf(qr[d], kr[d], a);
                    acc = a * 0.125f;
                }
            }
            sc[j] = acc;
            m = fmaxf(m, acc);
        }
#pragma unroll
        for (int o = 16; o; o >>= 1)
            m = fmaxf(m, __shfl_xor_sync(0xffffffffu, m, o));

        float l = 0.0f;
#pragma unroll
        for (int j = 0; j < 9; j++) {
            float e = __expf(sc[j] - m);
            sc[j] = e;
            l += e;
        }
#pragma unroll
        for (int o = 16; o; o >>= 1)
            l += __shfl_xor_sync(0xffffffffu, l, o);
        const float inv = 1.0f / l;

        float o0 = 0.0f, o1 = 0.0f;
#pragma unroll
        for (int j = 0; j < 9; j++) {
            if (j * 32 < nv) {
                int smax = nv - j * 32;
                if (smax > 32) smax = 32;
                float pj = sc[j];
                for (int t = 0; t < smax; t++) {
                    float p = __shfl_sync(0xffffffffu, pj, t);
                    const float* vr = Vs + (j * 32 + t) * 65;
                    o0 = fmaf(p, vr[lane], o0);
                    o1 = fmaf(p, vr[lane + 32], o1);
                }
            }
        }

        float* orow = g_xatt + ((size_t)((b * H_ + h) * G_ + g) * L_ + r) * D_;
        orow[lane]      = o0 * inv;
        orow[lane + 32] = o1 * inv;
    }
}

// ===========================================================================
// Tail: yq/yk and 7x7 group-level causal attention (yv). One warp per (b,h).
// ===========================================================================
__global__ void tail_kernel(float* __restrict__ out)
{
    const int bh = blockIdx.x;
    const int b = bh >> 4, h = bh & 15;
    const int lane = threadIdx.x;

    float ql0[7], ql1[7], kl0[7], kl1[7], xv0[7], xv1[7];
#pragma unroll
    for (int gi = 0; gi < 7; gi++) {
        int mo = ((b * H_ + h) * G_ + gi) * D_;
        ql0[gi] = g_mean[mo + lane];
        ql1[gi] = g_mean[mo + lane + 32];
        kl0[gi] = g_mean[B_ * H_ * G_ * D_ + mo + lane];
        kl1[gi] = g_mean[B_ * H_ * G_ * D_ + mo + lane + 32];
        size_t xa = ((size_t)((b * H_ + h) * G_ + gi) * L_ + 256) * D_;
        xv0[gi] = g_xatt[xa + lane];
        xv1[gi] = g_xatt[xa + lane + 32];

        out[YQ_OFF + (bh * 7 + gi) * 64 + lane]      = ql0[gi];
        out[YQ_OFF + (bh * 7 + gi) * 64 + lane + 32] = ql1[gi];
        out[YK_OFF + (bh * 7 + gi) * 64 + lane]      = kl0[gi];
        out[YK_OFF + (bh * 7 + gi) * 64 + lane + 32] = kl1[gi];
    }

#pragma unroll
    for (int i = 0; i < 7; i++) {
        float sc[7];
        float m = -1e30f;
#pragma unroll
        for (int j = 0; j < 7; j++) {
            float v = -1e30f;
            if (j <= i) {
                float p = ql0[i] * kl0[j] + ql1[i] * kl1[j];
#pragma unroll
                for (int o = 16; o; o >>= 1)
                    p += __shfl_xor_sync(0xffffffffu, p, o);
                v = p * 0.125f;
            }
            sc[j] = v;
            m = fmaxf(m, v);
        }
        float l = 0.0f;
#pragma unroll
        for (int j = 0; j < 7; j++) {
            float e = __expf(sc[j] - m);
            sc[j] = e;
            l += e;
        }
        float inv = 1.0f / l;
        float o0 = 0.0f, o1 = 0.0f;
#pragma unroll
        for (int j = 0; j < 7; j++) {
            o0 = fmaf(sc[j], xv0[j], o0);
            o1 = fmaf(sc[j], xv1[j], o1);
        }
        out[YV_OFF + (bh * 7 + i) * 64 + lane]      = o0 * inv;
        out[YV_OFF + (bh * 7 + i) * 64 + lane + 32] = o1 * inv;
    }
}

// ===========================================================================
extern "C" void kernel_launch(void* const* d_in, const int* in_sizes, int n_in,
                              void* d_out, int out_size)
{
    const float* x  = (const float*)d_in[0];
    const float* Wa = (const float*)d_in[1];
    const float* Wp = (const float*)d_in[2];
    float* out = (float*)d_out;

    void *p_qkv, *p_A, *p_B;
    cudaGetSymbolAddress(&p_qkv, g_qkv);
    cudaGetSymbolAddress(&p_A, g_Af16);
    cudaGetSymbolAddress(&p_B, g_Bf16);

    cudaFuncSetAttribute(attn_kernel,
                         cudaFuncAttributeMaxDynamicSharedMemorySize, (int)SMEM_ATTN);
    cudaFuncSetAttribute(gemm_f16,
                         cudaFuncAttributeMaxDynamicSharedMemorySize, GEMM_SMEM);

    // 1) convert x and W_attn to fp16
    conv_A<<<16384, 256>>>(x, (__half*)p_A);
    conv_W<<<dim3(C3_ / 32, C_ / 32), 256>>>(Wa, (__half*)p_B, C3_);

    // 2) qkv = x @ W_attn  (fp16 HMMA)
    gemm_f16<<<dim3(C3_ / 128, (B_ * T_) / 128), 256, GEMM_SMEM>>>(
        (const __half*)p_A, (const __half*)p_B, (float*)p_qkv, C3_);

    // 3) group means of q/k/v
    mean_kernel<<<768, 256>>>();

    // 4) causal attention per (b,h,g)
    attn_kernel<<<B_ * H_ * G_, 256, SMEM_ATTN>>>();

    // 5) yq / yk / yv
    tail_kernel<<<B_ * H_, 32>>>(out);

    // 6) fused rearrange + convert of xatt; convert W_proj
    conv_xatt<<<16384, 256>>>((__half*)p_A);
    conv_W<<<dim3(C_ / 32, C_ / 32), 256>>>(Wp, (__half*)p_B, C_);

    // 7) out = xo @ W_proj
    gemm_f16<<<dim3(C_ / 128, (B_ * T_) / 128), 256, GEMM_SMEM>>>(
        (const __half*)p_A, (const __half*)p_B, out, C_);
}

// round 6
// speedup vs baseline: 6.3314x; 2.6912x over previous
#include <cuda_runtime.h>
#include <cuda_fp16.h>
#include <math.h>
#include <stdint.h>

// Problem constants
#define B_   8
#define T_   2048
#define C_   1024
#define H_   16
#define D_   64
#define G_   8
#define GT_  256
#define C3_  3072

// Output layout in d_out (float32)
#define YQ_OFF  16777216
#define YK_OFF  (YQ_OFF + 57344)
#define YV_OFF  (YK_OFF + 57344)

// Device scratch
__device__ __half g_qkv16[(size_t)B_ * T_ * C3_];     // 96 MB
__device__ float g_mean[3 * B_ * H_ * G_ * D_];
__device__ float g_xmean[B_ * H_ * G_ * D_];          // xatt mean-token rows
__device__ __half g_Af16[(size_t)B_ * T_ * C_];       // 32 MB
__device__ __half g_Bf16[(size_t)C3_ * C_];           // 6 MB

// ===========================================================================
// mma / ldmatrix helpers
// ===========================================================================
__device__ __forceinline__ void ldsm_x4(uint32_t& r0, uint32_t& r1,
                                        uint32_t& r2, uint32_t& r3, uint32_t a) {
    asm volatile("ldmatrix.sync.aligned.m8n8.x4.shared.b16 {%0,%1,%2,%3}, [%4];"
                 : "=r"(r0), "=r"(r1), "=r"(r2), "=r"(r3) : "r"(a));
}
__device__ __forceinline__ void ldsm_x4_t(uint32_t& r0, uint32_t& r1,
                                          uint32_t& r2, uint32_t& r3, uint32_t a) {
    asm volatile("ldmatrix.sync.aligned.m8n8.x4.trans.shared.b16 {%0,%1,%2,%3}, [%4];"
                 : "=r"(r0), "=r"(r1), "=r"(r2), "=r"(r3) : "r"(a));
}
__device__ __forceinline__ void mma_f16(float* c, const uint32_t* a,
                                        const uint32_t* b) {
    asm volatile("mma.sync.aligned.m16n8k16.row.col.f32.f16.f16.f32 "
                 "{%0,%1,%2,%3}, {%4,%5,%6,%7}, {%8,%9}, {%0,%1,%2,%3};"
                 : "+f"(c[0]), "+f"(c[1]), "+f"(c[2]), "+f"(c[3])
                 : "r"(a[0]), "r"(a[1]), "r"(a[2]), "r"(a[3]),
                   "r"(b[0]), "r"(b[1]));
}
__device__ __forceinline__ void cp16(uint32_t saddr, const void* g) {
    asm volatile("cp.async.cg.shared.global [%0], [%1], 16;"
                 :: "r"(saddr), "l"(g));
}

// ===========================================================================
// HMMA fp16 GEMM:  C[M x N] = A[M x 1024] * Bt[N x 1024]^T
// CTA tile 128x128, 8 warps (2x4) of 64x32 warp tiles, K-chunk 32,
// 3-stage cp.async pipeline, padded smem row stride 40 halves (80 B).
// HALF_OUT: write fp16 (qkv) vs f32 (final out).
// ===========================================================================
#define KDIM    1024
#define NCHUNK  32
#define TILE_B  (128 * 40 * 2)
#define STAGE_B (2 * TILE_B)
#define GEMM_SMEM (3 * STAGE_B)   // 61440

template<bool HALF_OUT>
__global__ __launch_bounds__(256) void gemm_f16(
    const __half* __restrict__ A, const __half* __restrict__ Bt,
    void* __restrict__ Cv, int N)
{
    extern __shared__ char sm[];
    const uint32_t sb = (uint32_t)__cvta_generic_to_shared(sm);
    const int tid = threadIdx.x;
    const int wid = tid >> 5, lane = tid & 31;
    const int row0 = blockIdx.y * 128;
    const int col0 = blockIdx.x * 128;

    const int lr = tid >> 2;
    const int lc = (tid & 3) * 16;
    const char* gA = (const char*)A + (size_t)(row0 + lr) * 2048 + lc;
    const char* gB = (const char*)Bt + (size_t)(col0 + lr) * 2048 + lc;
    const uint32_t sRow = lr * 80 + lc;

    const int wm = (wid >> 2) * 64;
    const int wn = (wid & 3) * 32;
    const uint32_t aOffL = (wm + (lane & 15)) * 80 + (lane >> 4) * 16;
    const uint32_t bOffL = (wn + ((lane >> 3) & 1) * 8 + (lane & 7)) * 80
                         + (lane >> 4) * 16;

    float acc[4][4][4];
#pragma unroll
    for (int i = 0; i < 4; i++)
#pragma unroll
        for (int j = 0; j < 4; j++)
#pragma unroll
            for (int q = 0; q < 4; q++) acc[i][j][q] = 0.0f;

#pragma unroll
    for (int pc = 0; pc < 2; pc++) {
        const uint32_t st = sb + pc * STAGE_B;
        const size_t gk = (size_t)pc * 64;
#pragma unroll
        for (int it = 0; it < 2; it++) {
            uint32_t s = st + sRow + it * 64 * 80;
            size_t go = (size_t)it * 64 * 2048 + gk;
            cp16(s,          gA + go);
            cp16(s + TILE_B, gB + go);
        }
        asm volatile("cp.async.commit_group;");
    }

    for (int c = 0; c < NCHUNK; c++) {
        __syncthreads();
        if (c + 2 < NCHUNK) {
            const uint32_t st = sb + ((c + 2) % 3) * STAGE_B;
            const size_t gk = (size_t)(c + 2) * 64;
#pragma unroll
            for (int it = 0; it < 2; it++) {
                uint32_t s = st + sRow + it * 64 * 80;
                size_t go = (size_t)it * 64 * 2048 + gk;
                cp16(s,          gA + go);
                cp16(s + TILE_B, gB + go);
            }
            asm volatile("cp.async.commit_group;");
            asm volatile("cp.async.wait_group 2;");
        } else if (c + 1 < NCHUNK) {
            asm volatile("cp.async.wait_group 1;");
        } else {
            asm volatile("cp.async.wait_group 0;");
        }
        __syncthreads();

        const uint32_t st = sb + (c % 3) * STAGE_B;
#pragma unroll
        for (int ks = 0; ks < 2; ks++) {
            const uint32_t kb = ks * 32;
            uint32_t a[4][4], b[4][2];
#pragma unroll
            for (int mt = 0; mt < 4; mt++)
                ldsm_x4(a[mt][0], a[mt][1], a[mt][2], a[mt][3],
                        st + aOffL + mt * (16 * 80) + kb);
#pragma unroll
            for (int np = 0; np < 2; np++) {
                uint32_t r0, r1, r2, r3;
                ldsm_x4(r0, r1, r2, r3,
                        st + TILE_B + bOffL + np * (16 * 80) + kb);
                b[np * 2][0] = r0;     b[np * 2][1] = r2;
                b[np * 2 + 1][0] = r1; b[np * 2 + 1][1] = r3;
            }
#pragma unroll
            for (int mt = 0; mt < 4; mt++)
#pragma unroll
                for (int nt = 0; nt < 4; nt++)
                    mma_f16(acc[mt][nt], a[mt], b[nt]);
        }
    }

    const int erow = row0 + wm + (lane >> 2);
    const int ecol = col0 + wn + (lane & 3) * 2;
#pragma unroll
    for (int mt = 0; mt < 4; mt++) {
#pragma unroll
        for (int nt = 0; nt < 4; nt++) {
            if (HALF_OUT) {
                __half* p0 = (__half*)Cv + (size_t)(erow + mt * 16) * N + ecol + nt * 8;
                __half* p1 = p0 + 8 * N;
                *(__half2*)p0 = __floats2half2_rn(acc[mt][nt][0], acc[mt][nt][1]);
                *(__half2*)p1 = __floats2half2_rn(acc[mt][nt][2], acc[mt][nt][3]);
            } else {
                float* p0 = (float*)Cv + (size_t)(erow + mt * 16) * N + ecol + nt * 8;
                float* p1 = p0 + 8 * N;
                *(float2*)p0 = make_float2(acc[mt][nt][0], acc[mt][nt][1]);
                *(float2*)p1 = make_float2(acc[mt][nt][2], acc[mt][nt][3]);
            }
        }
    }
}

// ===========================================================================
// Conversions
// ===========================================================================
__global__ void conv_A(const float* __restrict__ src, __half* __restrict__ dst)
{
    int idx = blockIdx.x * blockDim.x + threadIdx.x;
    size_t e = (size_t)idx * 4;
    float4 v = *(const float4*)(src + e);
    __half2 h01 = __floats2half2_rn(v.x, v.y);
    __half2 h23 = __floats2half2_rn(v.z, v.w);
    uint2 o;
    o.x = *(uint32_t*)&h01;
    o.y = *(uint32_t*)&h23;
    *(uint2*)(dst + e) = o;
}

__global__ __launch_bounds__(256) void conv_W(
    const float* __restrict__ W, __half* __restrict__ dst, int Nw)
{
    __shared__ float tile[32][33];
    const int tx = threadIdx.x & 31, ty = threadIdx.x >> 5;
    const int k0 = blockIdx.y * 32, n0 = blockIdx.x * 32;
#pragma unroll
    for (int it = 0; it < 4; it++) {
        int r = ty + it * 8;
        tile[r][tx] = W[(size_t)(k0 + r) * Nw + n0 + tx];
    }
    __syncthreads();
#pragma unroll
    for (int it = 0; it < 4; it++) {
        int n = ty + it * 8;
        dst[(size_t)(n0 + n) * KDIM + k0 + tx] = __float2half_rn(tile[tx][n]);
    }
}

// ===========================================================================
// Per-(b,h,g,d) group means over 256 tokens (fp16 input, f32 accumulate)
// ===========================================================================
__global__ void mean_kernel()
{
    int idx = blockIdx.x * blockDim.x + threadIdx.x;
    int d     = idx & 63;
    int g     = (idx >> 6) & 7;
    int h     = (idx >> 9) & 15;
    int b     = (idx >> 13) & 7;
    int which = idx >> 16;

    const __half* base = g_qkv16 + (size_t)(b * T_ + g * GT_) * C3_
                       + which * C_ + h * D_ + d;
    float s = 0.0f;
    for (int i = 0; i < GT_; i++) s += __half2float(base[(size_t)i * C3_]);
    g_mean[which * (B_ * H_ * G_ * D_) + ((b * H_ + h) * G_ + g) * D_ + d]
        = s * (1.0f / 256.0f);
}

// ===========================================================================
// Flash attention per (b,h,g): L=257 padded to 272 = 17x16 row/col tiles.
// S = Q K^T (fp16 MMA, fp32 accum), online softmax, P.V via register-direct
// A-fragments + ldmatrix.trans on V. Writes rows<256 as fp16 into g_Af16
// ([t, h*64+d] layout for the proj GEMM); row 256 (mean token) f32 -> g_xmean.
// ===========================================================================
#define AST   72                    // halves per smem row (64 + 8 pad)
#define AROWS 272
#define ATT_SMEM (3 * AROWS * AST * 2)   // 117504 B

__global__ __launch_bounds__(256) void attn_mma()
{
    extern __shared__ __half sh2[];
    const int blk = blockIdx.x;
    const int g = blk & 7, h = (blk >> 3) & 15, b = blk >> 7;
    const int tid = threadIdx.x;
    const int warp = tid >> 5, lane = tid & 31;

    // ---- stage Q/K/V fp16 rows 0..255, mean token at 256, zeros 257..271 ----
    for (int ci = tid; ci < 3 * AROWS * 8; ci += 256) {
        int which = ci / (AROWS * 8);
        int rem = ci - which * (AROWS * 8);
        int s = rem >> 3, c = rem & 7;
        uint4 val;
        if (s < GT_) {
            val = *(const uint4*)(g_qkv16 +
                (size_t)(b * T_ + g * GT_ + s) * C3_ + which * C_ + h * D_ + c * 8);
        } else if (s == GT_) {
            const float* mp = g_mean + which * (B_ * H_ * G_ * D_)
                            + ((b * H_ + h) * G_ + g) * D_ + c * 8;
            float4 f0 = *(const float4*)mp;
            float4 f1 = *(const float4*)(mp + 4);
            __half2 q0 = __floats2half2_rn(f0.x, f0.y);
            __half2 q1 = __floats2half2_rn(f0.z, f0.w);
            __half2 q2 = __floats2half2_rn(f1.x, f1.y);
            __half2 q3 = __floats2half2_rn(f1.z, f1.w);
            val.x = *(uint32_t*)&q0; val.y = *(uint32_t*)&q1;
            val.z = *(uint32_t*)&q2; val.w = *(uint32_t*)&q3;
        } else {
            val = make_uint4(0, 0, 0, 0);
        }
        *(uint4*)(sh2 + (size_t)which * (AROWS * AST) + s * AST + c * 8) = val;
    }
    __syncthreads();

    const uint32_t sbase = (uint32_t)__cvta_generic_to_shared(sh2);
    const uint32_t qB = sbase;
    const uint32_t kB = sbase + AROWS * AST * 2;
    const uint32_t vB = kB + AROWS * AST * 2;

    const uint32_t aOff = (lane & 15) * (AST * 2) + (lane >> 4) * 16;
    const uint32_t bOff = (((lane >> 3) & 1) * 8 + (lane & 7)) * (AST * 2)
                        + (lane >> 4) * 16;
    const int rbase = lane >> 2;
    const int cbase = (lane & 3) * 2;

    const int nTiles = (warp == 0) ? 3 : 2;
    for (int ii = 0; ii < nTiles; ii++) {
        const int i = (ii == 0) ? warp : (ii == 1) ? (warp + 8) : 16;

        uint32_t qf[4][4];
#pragma unroll
        for (int ks = 0; ks < 4; ks++)
            ldsm_x4(qf[ks][0], qf[ks][1], qf[ks][2], qf[ks][3],
                    qB + i * (16 * AST * 2) + aOff + ks * 32);

        float m0 = -1e30f, m1 = -1e30f, l0 = 0.f, l1 = 0.f;
        float o[8][4];
#pragma unroll
        for (int nt = 0; nt < 8; nt++)
#pragma unroll
            for (int q = 0; q < 4; q++) o[nt][q] = 0.f;

        for (int j = 0; j <= i; j++) {
            float s0[4] = {0, 0, 0, 0}, s1[4] = {0, 0, 0, 0};
            const uint32_t kjb = kB + j * (16 * AST * 2) + bOff;
#pragma unroll
            for (int ks = 0; ks < 4; ks++) {
                uint32_t r0, r1, r2, r3;
                ldsm_x4(r0, r1, r2, r3, kjb + ks * 32);
                uint32_t bt0[2] = {r0, r2}, bt1[2] = {r1, r3};
                mma_f16(s0, qf[ks], bt0);
                mma_f16(s1, qf[ks], bt1);
            }
#pragma unroll
            for (int q = 0; q < 4; q++) { s0[q] *= 0.125f; s1[q] *= 0.125f; }
            if (j == i) {   // diagonal tile: causal mask (tile-relative indices)
#pragma unroll
                for (int q = 0; q < 4; q++) {
                    int row = rbase + (q >> 1) * 8;
                    int col = cbase + (q & 1);
                    if (col > row)     s0[q] = -1e30f;
                    if (col + 8 > row) s1[q] = -1e30f;
                }
            }
            float tm0 = fmaxf(fmaxf(s0[0], s0[1]), fmaxf(s1[0], s1[1]));
            float tm1 = fmaxf(fmaxf(s0[2], s0[3]), fmaxf(s1[2], s1[3]));
            tm0 = fmaxf(tm0, __shfl_xor_sync(0xffffffffu, tm0, 1));
            tm0 = fmaxf(tm0, __shfl_xor_sync(0xffffffffu, tm0, 2));
            tm1 = fmaxf(tm1, __shfl_xor_sync(0xffffffffu, tm1, 1));
            tm1 = fmaxf(tm1, __shfl_xor_sync(0xffffffffu, tm1, 2));
            const float nm0 = fmaxf(m0, tm0), nm1 = fmaxf(m1, tm1);
            const float a0 = __expf(m0 - nm0), a1 = __expf(m1 - nm1);
            m0 = nm0; m1 = nm1;
            const float p00 = __expf(s0[0] - nm0), p01 = __expf(s0[1] - nm0);
            const float p02 = __expf(s0[2] - nm1), p03 = __expf(s0[3] - nm1);
            const float p10 = __expf(s1[0] - nm0), p11 = __expf(s1[1] - nm0);
            const float p12 = __expf(s1[2] - nm1), p13 = __expf(s1[3] - nm1);
            l0 = l0 * a0 + (p00 + p01 + p10 + p11);
            l1 = l1 * a1 + (p02 + p03 + p12 + p13);
#pragma unroll
            for (int nt = 0; nt < 8; nt++) {
                o[nt][0] *= a0; o[nt][1] *= a0;
                o[nt][2] *= a1; o[nt][3] *= a1;
            }
            // S-accum fragment == A fragment layout for PV
            uint32_t pf[4];
            __half2 hh;
            hh = __floats2half2_rn(p00, p01); pf[0] = *(uint32_t*)&hh;
            hh = __floats2half2_rn(p02, p03); pf[1] = *(uint32_t*)&hh;
            hh = __floats2half2_rn(p10, p11); pf[2] = *(uint32_t*)&hh;
            hh = __floats2half2_rn(p12, p13); pf[3] = *(uint32_t*)&hh;

            const uint32_t vjb = vB + j * (16 * AST * 2) + bOff;
#pragma unroll
            for (int dp = 0; dp < 4; dp++) {
                uint32_t r0, r1, r2, r3;
                ldsm_x4_t(r0, r1, r2, r3, vjb + dp * 32);
                uint32_t bt0[2] = {r0, r1}, bt1[2] = {r2, r3};
                mma_f16(o[dp * 2],     pf, bt0);
                mma_f16(o[dp * 2 + 1], pf, bt1);
            }
        }

        l0 += __shfl_xor_sync(0xffffffffu, l0, 1);
        l0 += __shfl_xor_sync(0xffffffffu, l0, 2);
        l1 += __shfl_xor_sync(0xffffffffu, l1, 1);
        l1 += __shfl_xor_sync(0xffffffffu, l1, 2);
        const float inv0 = 1.0f / l0, inv1 = 1.0f / l1;

        const int row0 = 16 * i + rbase;
        const int row1 = row0 + 8;
        if (row0 < GT_) {
            __half* p = g_Af16 + (size_t)(b * T_ + g * GT_ + row0) * C_
                      + h * D_ + cbase;
#pragma unroll
            for (int nt = 0; nt < 8; nt++)
                *(__half2*)(p + nt * 8) =
                    __floats2half2_rn(o[nt][0] * inv0, o[nt][1] * inv0);
        } else if (row0 == GT_) {
            float* p = g_xmean + ((b * H_ + h) * G_ + g) * D_ + cbase;
#pragma unroll
            for (int nt = 0; nt < 8; nt++)
                *(float2*)(p + nt * 8) =
                    make_float2(o[nt][0] * inv0, o[nt][1] * inv0);
        }
        if (row1 < GT_) {
            __half* p = g_Af16 + (size_t)(b * T_ + g * GT_ + row1) * C_
                      + h * D_ + cbase;
#pragma unroll
            for (int nt = 0; nt < 8; nt++)
                *(__half2*)(p + nt * 8) =
                    __floats2half2_rn(o[nt][2] * inv1, o[nt][3] * inv1);
        }
    }
}

// ===========================================================================
// Tail: yq/yk and 7x7 group-level causal attention (yv). One warp per (b,h).
// ===========================================================================
__global__ void tail_kernel(float* __restrict__ out)
{
    const int bh = blockIdx.x;
    const int b = bh >> 4, h = bh & 15;
    const int lane = threadIdx.x;

    float ql0[7], ql1[7], kl0[7], kl1[7], xv0[7], xv1[7];
#pragma unroll
    for (int gi = 0; gi < 7; gi++) {
        int mo = ((b * H_ + h) * G_ + gi) * D_;
        ql0[gi] = g_mean[mo + lane];
        ql1[gi] = g_mean[mo + lane + 32];
        kl0[gi] = g_mean[B_ * H_ * G_ * D_ + mo + lane];
        kl1[gi] = g_mean[B_ * H_ * G_ * D_ + mo + lane + 32];
        xv0[gi] = g_xmean[mo + lane];
        xv1[gi] = g_xmean[mo + lane + 32];

        out[YQ_OFF + (bh * 7 + gi) * 64 + lane]      = ql0[gi];
        out[YQ_OFF + (bh * 7 + gi) * 64 + lane + 32] = ql1[gi];
        out[YK_OFF + (bh * 7 + gi) * 64 + lane]      = kl0[gi];
        out[YK_OFF + (bh * 7 + gi) * 64 + lane + 32] = kl1[gi];
    }

#pragma unroll
    for (int i = 0; i < 7; i++) {
        float sc[7];
        float m = -1e30f;
#pragma unroll
        for (int j = 0; j < 7; j++) {
            float v = -1e30f;
            if (j <= i) {
                float p = ql0[i] * kl0[j] + ql1[i] * kl1[j];
#pragma unroll
                for (int o = 16; o; o >>= 1)
                    p += __shfl_xor_sync(0xffffffffu, p, o);
                v = p * 0.125f;
            }
            sc[j] = v;
            m = fmaxf(m, v);
        }
        float l = 0.0f;
#pragma unroll
        for (int j = 0; j < 7; j++) {
            float e = __expf(sc[j] - m);
            sc[j] = e;
            l += e;
        }
        float inv = 1.0f / l;
        float o0 = 0.0f, o1 = 0.0f;
#pragma unroll
        for (int j = 0; j < 7; j++) {
            o0 = fmaf(sc[j], xv0[j], o0);
            o1 = fmaf(sc[j], xv1[j], o1);
        }
        out[YV_OFF + (bh * 7 + i) * 64 + lane]      = o0 * inv;
        out[YV_OFF + (bh * 7 + i) * 64 + lane + 32] = o1 * inv;
    }
}

// ===========================================================================
extern "C" void kernel_launch(void* const* d_in, const int* in_sizes, int n_in,
                              void* d_out, int out_size)
{
    const float* x  = (const float*)d_in[0];
    const float* Wa = (const float*)d_in[1];
    const float* Wp = (const float*)d_in[2];
    float* out = (float*)d_out;

    void *p_qkv, *p_A, *p_B;
    cudaGetSymbolAddress(&p_qkv, g_qkv16);
    cudaGetSymbolAddress(&p_A, g_Af16);
    cudaGetSymbolAddress(&p_B, g_Bf16);

    cudaFuncSetAttribute(gemm_f16<true>,
                         cudaFuncAttributeMaxDynamicSharedMemorySize, GEMM_SMEM);
    cudaFuncSetAttribute(gemm_f16<false>,
                         cudaFuncAttributeMaxDynamicSharedMemorySize, GEMM_SMEM);
    cudaFuncSetAttribute(attn_mma,
                         cudaFuncAttributeMaxDynamicSharedMemorySize, ATT_SMEM);

    // 1) convert x and W_attn to fp16
    conv_A<<<16384, 256>>>(x, (__half*)p_A);
    conv_W<<<dim3(C3_ / 32, C_ / 32), 256>>>(Wa, (__half*)p_B, C3_);

    // 2) qkv = x @ W_attn  (fp16 HMMA, fp16 output)
    gemm_f16<true><<<dim3(C3_ / 128, (B_ * T_) / 128), 256, GEMM_SMEM>>>(
        (const __half*)p_A, (const __half*)p_B, p_qkv, C3_);

    // 3) group means of q/k/v
    mean_kernel<<<768, 256>>>();

    // 4) flash attention per (b,h,g) -> writes xo fp16 directly + mean rows
    attn_mma<<<B_ * H_ * G_, 256, ATT_SMEM>>>();

    // 5) yq / yk / yv
    tail_kernel<<<B_ * H_, 32>>>(out);

    // 6) convert W_proj; out = xo @ W_proj (f32 output)
    conv_W<<<dim3(C_ / 32, C_ / 32), 256>>>(Wp, (__half*)p_B, C_);
    gemm_f16<false><<<dim3(C_ / 128, (B_ * T_) / 128), 256, GEMM_SMEM>>>(
        (const __half*)p_A, (const __half*)p_B, out, C_);
}